// round 4
// baseline (speedup 1.0000x reference)
#include <cuda_runtime.h>

#define NN   50000
#define EE   800000
#define TE   (EE + NN)
#define CIN  128
#define COUT 64

// ---- device scratch (16B-aligned for float4 access) ----
__device__ __align__(16) float g_xl[NN * COUT];     // x @ W_l
__device__ __align__(16) float g_xr[NN * COUT];     // x @ W_r
__device__ __align__(16) int   g_cnt[NN];           // per-dst degree
__device__ __align__(16) int   g_rowptr[NN + 1];    // CSR row pointers
__device__ __align__(16) int   g_cursor[NN];        // fill cursors
__device__ __align__(16) int   g_srcs[TE];          // CSR: src per slot
__device__ __align__(16) float g_logit[TE];         // CSR: logit per slot

__device__ __forceinline__ int clampN(int v) {
    return v < 0 ? 0 : (v >= NN ? NN - 1 : v);
}

// ---------------------------------------------------------------- K0: init
__global__ void k_init() {
    int i = blockIdx.x * blockDim.x + threadIdx.x;
    if (i < NN) g_cnt[i] = 0;
}

// ----------------------------------------------------- K1: count edges/dst
__global__ void k_count(const int* __restrict__ ei) {
    int e = blockIdx.x * blockDim.x + threadIdx.x;
    if (e >= TE) return;
    int d = (e < EE) ? clampN(ei[EE + e]) : (e - EE);
    atomicAdd(&g_cnt[d], 1);
}

// ------------------------------------- K2: exclusive scan (single block)
__global__ void k_scan() {
    __shared__ int warp_sums[32];
    __shared__ int s_carry;
    int tid = threadIdx.x, lane = tid & 31, wid = tid >> 5;
    if (tid == 0) s_carry = 0;
    __syncthreads();

    for (int base = 0; base < NN; base += 1024) {
        int i = base + tid;
        int v = (i < NN) ? g_cnt[i] : 0;
        int x = v;
        #pragma unroll
        for (int off = 1; off < 32; off <<= 1) {
            int y = __shfl_up_sync(0xffffffffu, x, off);
            if (lane >= off) x += y;
        }
        if (lane == 31) warp_sums[wid] = x;
        __syncthreads();
        if (wid == 0) {
            int w = warp_sums[lane];
            #pragma unroll
            for (int off = 1; off < 32; off <<= 1) {
                int y = __shfl_up_sync(0xffffffffu, w, off);
                if (lane >= off) w += y;
            }
            warp_sums[lane] = w;
        }
        __syncthreads();
        int warp_off = (wid > 0) ? warp_sums[wid - 1] : 0;
        int excl = s_carry + warp_off + x - v;
        if (i < NN) { g_rowptr[i] = excl; g_cursor[i] = excl; }
        __syncthreads();
        if (tid == 0) s_carry += warp_sums[31];
        __syncthreads();
    }
    if (tid == 0) g_rowptr[NN] = s_carry;   // == TE
}

// ------------------------------------------- K3: x@[W_l|W_r] fused GEMM
// 64 rows/block, 256 threads, static 48KB smem, K chunked in halves of 64.
__global__ void k_gemm(const float* __restrict__ x,
                       const float* __restrict__ Wl,
                       const float* __restrict__ Wr) {
    __shared__ float Ws[64 * 128];   // 32KB: W rows [kc*64, kc*64+64), 128 cols
    __shared__ float xs[64 * 64];    // 16KB: x tile 64 rows x 64 K-cols

    const int tid  = threadIdx.x;
    const int base = blockIdx.x * 64;
    const int tx = tid & 31, ty = tid >> 5;

    float acc[8][4];
    #pragma unroll
    for (int i = 0; i < 8; i++)
        #pragma unroll
        for (int j = 0; j < 4; j++) acc[i][j] = 0.0f;

    for (int kc = 0; kc < 2; kc++) {
        const int k0 = kc * 64;
        // combined W chunk: cols [0,64) = W_l, [64,128) = W_r
        for (int idx = tid * 4; idx < 64 * 128; idx += 256 * 4) {
            int k = k0 + (idx >> 7), c = idx & 127;
            const float* p = (c < 64) ? (Wl + k * 64 + c)
                                      : (Wr + k * 64 + (c - 64));
            *(float4*)&Ws[idx] = *(const float4*)p;
        }
        // x tile chunk
        for (int idx = tid * 4; idx < 64 * 64; idx += 256 * 4) {
            int r = idx >> 6;
            int row = base + r;
            float4 v = make_float4(0.f, 0.f, 0.f, 0.f);
            if (row < NN) v = *(const float4*)&x[row * CIN + k0 + (idx & 63)];
            *(float4*)&xs[idx] = v;
        }
        __syncthreads();

        #pragma unroll 4
        for (int k = 0; k < 64; k++) {
            float wv[4];
            #pragma unroll
            for (int j = 0; j < 4; j++) wv[j] = Ws[k * 128 + tx + 32 * j];
            #pragma unroll
            for (int i = 0; i < 8; i++) {
                float xv = xs[(ty + 8 * i) * 64 + k];
                #pragma unroll
                for (int j = 0; j < 4; j++) acc[i][j] += xv * wv[j];
            }
        }
        __syncthreads();
    }

    #pragma unroll
    for (int i = 0; i < 8; i++) {
        int row = base + ty + 8 * i;
        if (row >= NN) continue;
        #pragma unroll
        for (int j = 0; j < 4; j++) {
            int c = tx + 32 * j;
            if (c < 64) g_xl[row * 64 + c]        = acc[i][j];
            else        g_xr[row * 64 + (c - 64)] = acc[i][j];
        }
    }
}

// --------------------- K4: per-edge logit + CSR fill (16 lanes per edge)
// grid is an exact multiple of block size (TE*16 % 256 == 0): no early exits.
__global__ void k_edge(const int* __restrict__ ei,
                       const float* __restrict__ att) {
    int t = blockIdx.x * blockDim.x + threadIdx.x;
    int e = t >> 4;
    int lane = t & 15;

    int s, d;
    if (e < EE) { s = clampN(ei[e]); d = clampN(ei[EE + e]); }
    else        { s = d = e - EE; }

    int pos = 0;
    if (lane == 0) pos = atomicAdd(&g_cursor[d], 1);
    pos = __shfl_sync(0xffffffffu, pos, 0, 16);

    float4 xl = *(const float4*)&g_xl[s * 64 + lane * 4];
    float4 xr = *(const float4*)&g_xr[d * 64 + lane * 4];
    float4 av = *(const float4*)&att[lane * 4];

    float v0 = xl.x + xr.x; v0 = v0 > 0.f ? v0 : 0.2f * v0;
    float v1 = xl.y + xr.y; v1 = v1 > 0.f ? v1 : 0.2f * v1;
    float v2 = xl.z + xr.z; v2 = v2 > 0.f ? v2 : 0.2f * v2;
    float v3 = xl.w + xr.w; v3 = v3 > 0.f ? v3 : 0.2f * v3;
    float sum = v0 * av.x + v1 * av.y + v2 * av.z + v3 * av.w;

    sum += __shfl_xor_sync(0xffffffffu, sum, 8);
    sum += __shfl_xor_sync(0xffffffffu, sum, 4);
    sum += __shfl_xor_sync(0xffffffffu, sum, 2);
    sum += __shfl_xor_sync(0xffffffffu, sum, 1);

    if (lane == 0) {
        g_srcs[pos]  = s;
        g_logit[pos] = sum;
    }
}

// -------- K5: per-dst aggregation + epilogue (one warp per node, no atomics)
// grid exact multiple of block (NN*32 % 256 == 0): no early exits.
__global__ void k_aggr(float* __restrict__ out, const float* __restrict__ bias) {
    int node = (blockIdx.x * blockDim.x + threadIdx.x) >> 5;
    int lane = threadIdx.x & 31;

    int beg = g_rowptr[node], end = g_rowptr[node + 1];

    // segment max (warp-parallel over edges)
    float m = -3.4e38f;
    for (int p = beg + lane; p < end; p += 32) m = fmaxf(m, g_logit[p]);
    #pragma unroll
    for (int off = 16; off >= 1; off >>= 1)
        m = fmaxf(m, __shfl_xor_sync(0xffffffffu, m, off));

    // weighted accumulation: lane owns channels {lane, lane+32}
    float denom = 0.f, acc0 = 0.f, acc1 = 0.f;
    #pragma unroll 2
    for (int p = beg; p < end; p++) {
        float a  = __expf(g_logit[p] - m);
        int   sv = g_srcs[p];
        denom += a;
        acc0  += a * g_xl[sv * 64 + lane];
        acc1  += a * g_xl[sv * 64 + 32 + lane];
    }

    float inv = 1.0f / (denom + 1e-16f);
    float v0 = acc0 * inv + bias[lane];
    float v1 = acc1 * inv + bias[lane + 32];

    float h0 = v0 > 0.f ? v0 : (__expf(v0) - 1.0f);
    float h1 = v1 > 0.f ? v1 : (__expf(v1) - 1.0f);

    float mx = fmaxf(h0, h1);
    #pragma unroll
    for (int off = 16; off >= 1; off >>= 1)
        mx = fmaxf(mx, __shfl_xor_sync(0xffffffffu, mx, off));
    float sm = __expf(h0 - mx) + __expf(h1 - mx);
    #pragma unroll
    for (int off = 16; off >= 1; off >>= 1)
        sm += __shfl_xor_sync(0xffffffffu, sm, off);
    float lse = mx + __logf(sm);

    out[node * 64 + lane]      = h0 - lse;
    out[node * 64 + lane + 32] = h1 - lse;
}

// --------------------------------------------------------------------------
extern "C" void kernel_launch(void* const* d_in, const int* in_sizes, int n_in,
                              void* d_out, int out_size) {
    const float* x    = (const float*)d_in[0];
    const int*   ei   = (const int*)d_in[1];     // int32 (JAX x64 disabled)
    const float* Wl   = (const float*)d_in[2];
    const float* Wr   = (const float*)d_in[3];
    const float* att  = (const float*)d_in[4];
    const float* bias = (const float*)d_in[5];
    float*       out  = (float*)d_out;

    k_init<<<(NN + 511) / 512, 512>>>();
    k_count<<<(TE + 255) / 256, 256>>>(ei);
    k_gemm<<<(NN + 63) / 64, 256>>>(x, Wl, Wr);
    k_scan<<<1, 1024>>>();
    k_edge<<<TE * 16 / 256, 256>>>(ei, att);
    k_aggr<<<NN * 32 / 256, 256>>>(out, bias);
}

// round 6
// speedup vs baseline: 1.1997x; 1.1997x over previous
#include <cuda_runtime.h>

#define NN   50000
#define EE   800000
#define TE   (EE + NN)
#define CIN  128
#define COUT 64

#define SCAN_B   512
#define SCAN_G   ((NN + SCAN_B - 1) / SCAN_B)   // 98

// ---- device scratch (16B-aligned for float4 access) ----
__device__ __align__(16) float g_xl[NN * COUT];     // x @ W_l
__device__ __align__(16) float g_xr[NN * COUT];     // x @ W_r
__device__ __align__(16) int   g_cnt[NN];           // per-dst degree
__device__ __align__(16) int   g_rowptr[NN + 1];    // CSR row pointers
__device__ __align__(16) int   g_cursor[NN];        // fill cursors
__device__ __align__(16) int   g_srcs[TE];          // CSR: src per slot
__device__ __align__(16) float g_logit[TE];         // CSR: logit per slot
__device__ __align__(16) int   g_bsum[SCAN_G];      // per-block totals
__device__ __align__(16) int   g_boff[SCAN_G];      // per-block offsets

__device__ __forceinline__ int clampN(int v) {
    return v < 0 ? 0 : (v >= NN ? NN - 1 : v);
}

// ---------------------------------------------------------------- K0: init
__global__ void k_init() {
    int i = blockIdx.x * blockDim.x + threadIdx.x;
    if (i < NN) g_cnt[i] = 0;
}

// ----------------------------------------------------- K1: count edges/dst
__global__ void k_count(const int* __restrict__ ei) {
    int e = blockIdx.x * blockDim.x + threadIdx.x;
    if (e >= TE) return;
    int d = (e < EE) ? clampN(ei[EE + e]) : (e - EE);
    atomicAdd(&g_cnt[d], 1);
}

// ------------------- K2a: block-local exclusive scan + block totals
__global__ void k_scanA() {
    __shared__ int warp_sums[16];
    int tid = threadIdx.x, lane = tid & 31, wid = tid >> 5;
    int i = blockIdx.x * SCAN_B + tid;

    int v = (i < NN) ? g_cnt[i] : 0;
    int x = v;
    #pragma unroll
    for (int off = 1; off < 32; off <<= 1) {
        int y = __shfl_up_sync(0xffffffffu, x, off);
        if (lane >= off) x += y;
    }
    if (lane == 31) warp_sums[wid] = x;
    __syncthreads();
    if (wid == 0 && lane < 16) {
        int w = warp_sums[lane];
        #pragma unroll
        for (int off = 1; off < 16; off <<= 1) {
            int y = __shfl_up_sync(0x0000ffffu, w, off);
            if (lane >= off) w += y;
        }
        warp_sums[lane] = w;
    }
    __syncthreads();
    int warp_off = (wid > 0) ? warp_sums[wid - 1] : 0;
    if (i < NN) g_rowptr[i] = warp_off + x - v;   // local exclusive
    if (tid == 0) g_bsum[blockIdx.x] = warp_sums[15];
}

// ------------------- K2b: exclusive scan of 98 block totals (1 tiny block)
__global__ void k_scanB() {
    __shared__ int s[128];
    int t = threadIdx.x;
    s[t] = (t < SCAN_G) ? g_bsum[t] : 0;
    __syncthreads();
    #pragma unroll
    for (int off = 1; off < 128; off <<= 1) {
        int v = (t >= off) ? s[t - off] : 0;
        __syncthreads();
        s[t] += v;
        __syncthreads();
    }
    if (t < SCAN_G) g_boff[t] = s[t] - g_bsum[t];   // exclusive
    if (t == 0) g_rowptr[NN] = TE;                  // total is static
}

// ------------------- K2c: apply block offsets, materialize cursors
__global__ void k_scanC() {
    int i = blockIdx.x * SCAN_B + threadIdx.x;
    if (i >= NN) return;
    int r = g_rowptr[i] + g_boff[blockIdx.x];
    g_rowptr[i] = r;
    g_cursor[i] = r;
}

// ------------------------------------------- K3: x@[W_l|W_r] fused GEMM
// 64 rows/block, 256 threads, static 48KB smem, K chunked in halves of 64.
__global__ void k_gemm(const float* __restrict__ x,
                       const float* __restrict__ Wl,
                       const float* __restrict__ Wr) {
    __shared__ float Ws[64 * 128];   // 32KB
    __shared__ float xs[64 * 64];    // 16KB

    const int tid  = threadIdx.x;
    const int base = blockIdx.x * 64;
    const int tx = tid & 31, ty = tid >> 5;

    float acc[8][4];
    #pragma unroll
    for (int i = 0; i < 8; i++)
        #pragma unroll
        for (int j = 0; j < 4; j++) acc[i][j] = 0.0f;

    for (int kc = 0; kc < 2; kc++) {
        const int k0 = kc * 64;
        for (int idx = tid * 4; idx < 64 * 128; idx += 256 * 4) {
            int k = k0 + (idx >> 7), c = idx & 127;
            const float* p = (c < 64) ? (Wl + k * 64 + c)
                                      : (Wr + k * 64 + (c - 64));
            *(float4*)&Ws[idx] = *(const float4*)p;
        }
        for (int idx = tid * 4; idx < 64 * 64; idx += 256 * 4) {
            int r = idx >> 6;
            int row = base + r;
            float4 v = make_float4(0.f, 0.f, 0.f, 0.f);
            if (row < NN) v = *(const float4*)&x[row * CIN + k0 + (idx & 63)];
            *(float4*)&xs[idx] = v;
        }
        __syncthreads();

        #pragma unroll 4
        for (int k = 0; k < 64; k++) {
            float wv[4];
            #pragma unroll
            for (int j = 0; j < 4; j++) wv[j] = Ws[k * 128 + tx + 32 * j];
            #pragma unroll
            for (int i = 0; i < 8; i++) {
                float xv = xs[(ty + 8 * i) * 64 + k];
                #pragma unroll
                for (int j = 0; j < 4; j++) acc[i][j] += xv * wv[j];
            }
        }
        __syncthreads();
    }

    #pragma unroll
    for (int i = 0; i < 8; i++) {
        int row = base + ty + 8 * i;
        if (row >= NN) continue;
        #pragma unroll
        for (int j = 0; j < 4; j++) {
            int c = tx + 32 * j;
            if (c < 64) g_xl[row * 64 + c]        = acc[i][j];
            else        g_xr[row * 64 + (c - 64)] = acc[i][j];
        }
    }
}

// --------------------- K4: per-edge logit + CSR fill (16 lanes per edge)
__global__ void k_edge(const int* __restrict__ ei,
                       const float* __restrict__ att) {
    int t = blockIdx.x * blockDim.x + threadIdx.x;
    int e = t >> 4;
    int lane = t & 15;

    int s, d;
    if (e < EE) { s = clampN(ei[e]); d = clampN(ei[EE + e]); }
    else        { s = d = e - EE; }

    int pos = 0;
    if (lane == 0) pos = atomicAdd(&g_cursor[d], 1);
    pos = __shfl_sync(0xffffffffu, pos, 0, 16);

    float4 xl = *(const float4*)&g_xl[s * 64 + lane * 4];
    float4 xr = *(const float4*)&g_xr[d * 64 + lane * 4];
    float4 av = *(const float4*)&att[lane * 4];

    float v0 = xl.x + xr.x; v0 = v0 > 0.f ? v0 : 0.2f * v0;
    float v1 = xl.y + xr.y; v1 = v1 > 0.f ? v1 : 0.2f * v1;
    float v2 = xl.z + xr.z; v2 = v2 > 0.f ? v2 : 0.2f * v2;
    float v3 = xl.w + xr.w; v3 = v3 > 0.f ? v3 : 0.2f * v3;
    float sum = v0 * av.x + v1 * av.y + v2 * av.z + v3 * av.w;

    sum += __shfl_xor_sync(0xffffffffu, sum, 8);
    sum += __shfl_xor_sync(0xffffffffu, sum, 4);
    sum += __shfl_xor_sync(0xffffffffu, sum, 2);
    sum += __shfl_xor_sync(0xffffffffu, sum, 1);

    if (lane == 0) {
        g_srcs[pos]  = s;
        g_logit[pos] = sum;
    }
}

// -------- K5: per-dst aggregation + epilogue (one warp per node, no atomics)
__global__ void k_aggr(float* __restrict__ out, const float* __restrict__ bias) {
    int node = (blockIdx.x * blockDim.x + threadIdx.x) >> 5;
    int lane = threadIdx.x & 31;

    int beg = g_rowptr[node], end = g_rowptr[node + 1];

    float m = -3.4e38f;
    for (int p = beg + lane; p < end; p += 32) m = fmaxf(m, g_logit[p]);
    #pragma unroll
    for (int off = 16; off >= 1; off >>= 1)
        m = fmaxf(m, __shfl_xor_sync(0xffffffffu, m, off));

    float denom = 0.f, acc0 = 0.f, acc1 = 0.f;
    #pragma unroll 2
    for (int p = beg; p < end; p++) {
        float a  = __expf(g_logit[p] - m);
        int   sv = g_srcs[p];
        denom += a;
        acc0  += a * g_xl[sv * 64 + lane];
        acc1  += a * g_xl[sv * 64 + 32 + lane];
    }

    float inv = 1.0f / (denom + 1e-16f);
    float v0 = acc0 * inv + bias[lane];
    float v1 = acc1 * inv + bias[lane + 32];

    float h0 = v0 > 0.f ? v0 : (__expf(v0) - 1.0f);
    float h1 = v1 > 0.f ? v1 : (__expf(v1) - 1.0f);

    float mx = fmaxf(h0, h1);
    #pragma unroll
    for (int off = 16; off >= 1; off >>= 1)
        mx = fmaxf(mx, __shfl_xor_sync(0xffffffffu, mx, off));
    float sm = __expf(h0 - mx) + __expf(h1 - mx);
    #pragma unroll
    for (int off = 16; off >= 1; off >>= 1)
        sm += __shfl_xor_sync(0xffffffffu, sm, off);
    float lse = mx + __logf(sm);

    out[node * 64 + lane]      = h0 - lse;
    out[node * 64 + lane + 32] = h1 - lse;
}

// --------------------------------------------------------------------------
extern "C" void kernel_launch(void* const* d_in, const int* in_sizes, int n_in,
                              void* d_out, int out_size) {
    const float* x    = (const float*)d_in[0];
    const int*   ei   = (const int*)d_in[1];     // int32 (JAX x64 disabled)
    const float* Wl   = (const float*)d_in[2];
    const float* Wr   = (const float*)d_in[3];
    const float* att  = (const float*)d_in[4];
    const float* bias = (const float*)d_in[5];
    float*       out  = (float*)d_out;

    k_init<<<(NN + 511) / 512, 512>>>();
    k_count<<<(TE + 255) / 256, 256>>>(ei);
    k_gemm<<<(NN + 63) / 64, 256>>>(x, Wl, Wr);
    k_scanA<<<SCAN_G, SCAN_B>>>();
    k_scanB<<<1, 128>>>();
    k_scanC<<<SCAN_G, SCAN_B>>>();
    k_edge<<<TE * 16 / 256, 256>>>(ei, att);
    k_aggr<<<NN * 32 / 256, 256>>>(out, bias);
}

// round 7
// speedup vs baseline: 1.3464x; 1.1223x over previous
#include <cuda_runtime.h>

#define NN   50000
#define EE   800000
#define TE   (EE + NN)
#define CIN  128
#define COUT 64

#define SCAN_B   512
#define SCAN_G   ((NN + SCAN_B - 1) / SCAN_B)   // 98

// ---- device scratch (16B-aligned for float4 access) ----
__device__ __align__(16) float g_xl[NN * COUT];     // x @ W_l
__device__ __align__(16) float g_xr[NN * COUT];     // x @ W_r
__device__ __align__(16) int   g_cnt[NN];           // per-dst degree
__device__ __align__(16) int   g_rowptr[NN + 1];    // CSR row pointers
__device__ __align__(16) int   g_cursor[NN];        // fill cursors
__device__ __align__(16) int   g_srcs[TE];          // CSR: src per slot
__device__ __align__(16) int   g_bsum[SCAN_G];      // per-block totals
__device__ __align__(16) int   g_boff[SCAN_G];      // per-block offsets

__device__ __forceinline__ int clampN(int v) {
    return v < 0 ? 0 : (v >= NN ? NN - 1 : v);
}

// ---------------------------------------------------------------- K0: init
__global__ void k_init() {
    int i = blockIdx.x * blockDim.x + threadIdx.x;
    if (i < NN) g_cnt[i] = 0;
}

// ----------------------------------------------------- K1: count edges/dst
__global__ void k_count(const int* __restrict__ ei) {
    int e = blockIdx.x * blockDim.x + threadIdx.x;
    if (e >= TE) return;
    int d = (e < EE) ? clampN(ei[EE + e]) : (e - EE);
    atomicAdd(&g_cnt[d], 1);
}

// ------------------- K2a: block-local exclusive scan + block totals
__global__ void k_scanA() {
    __shared__ int warp_sums[16];
    int tid = threadIdx.x, lane = tid & 31, wid = tid >> 5;
    int i = blockIdx.x * SCAN_B + tid;

    int v = (i < NN) ? g_cnt[i] : 0;
    int x = v;
    #pragma unroll
    for (int off = 1; off < 32; off <<= 1) {
        int y = __shfl_up_sync(0xffffffffu, x, off);
        if (lane >= off) x += y;
    }
    if (lane == 31) warp_sums[wid] = x;
    __syncthreads();
    if (wid == 0 && lane < 16) {
        int w = warp_sums[lane];
        #pragma unroll
        for (int off = 1; off < 16; off <<= 1) {
            int y = __shfl_up_sync(0x0000ffffu, w, off);
            if (lane >= off) w += y;
        }
        warp_sums[lane] = w;
    }
    __syncthreads();
    int warp_off = (wid > 0) ? warp_sums[wid - 1] : 0;
    if (i < NN) g_rowptr[i] = warp_off + x - v;   // local exclusive
    if (tid == 0) g_bsum[blockIdx.x] = warp_sums[15];
}

// ------------------- K2b: exclusive scan of 98 block totals
__global__ void k_scanB() {
    __shared__ int s[128];
    int t = threadIdx.x;
    s[t] = (t < SCAN_G) ? g_bsum[t] : 0;
    __syncthreads();
    #pragma unroll
    for (int off = 1; off < 128; off <<= 1) {
        int v = (t >= off) ? s[t - off] : 0;
        __syncthreads();
        s[t] += v;
        __syncthreads();
    }
    if (t < SCAN_G) g_boff[t] = s[t] - g_bsum[t];   // exclusive
    if (t == 0) g_rowptr[NN] = TE;
}

// ------------------- K2c: apply block offsets, materialize cursors
__global__ void k_scanC() {
    int i = blockIdx.x * SCAN_B + threadIdx.x;
    if (i >= NN) return;
    int r = g_rowptr[i] + g_boff[blockIdx.x];
    g_rowptr[i] = r;
    g_cursor[i] = r;
}

// ------------------------------------------- K3: x@[W_l|W_r] fused GEMM
__global__ void k_gemm(const float* __restrict__ x,
                       const float* __restrict__ Wl,
                       const float* __restrict__ Wr) {
    __shared__ float Ws[64 * 128];   // 32KB
    __shared__ float xs[64 * 64];    // 16KB

    const int tid  = threadIdx.x;
    const int base = blockIdx.x * 64;
    const int tx = tid & 31, ty = tid >> 5;

    float acc[8][4];
    #pragma unroll
    for (int i = 0; i < 8; i++)
        #pragma unroll
        for (int j = 0; j < 4; j++) acc[i][j] = 0.0f;

    for (int kc = 0; kc < 2; kc++) {
        const int k0 = kc * 64;
        for (int idx = tid * 4; idx < 64 * 128; idx += 256 * 4) {
            int k = k0 + (idx >> 7), c = idx & 127;
            const float* p = (c < 64) ? (Wl + k * 64 + c)
                                      : (Wr + k * 64 + (c - 64));
            *(float4*)&Ws[idx] = *(const float4*)p;
        }
        for (int idx = tid * 4; idx < 64 * 64; idx += 256 * 4) {
            int r = idx >> 6;
            int row = base + r;
            float4 v = make_float4(0.f, 0.f, 0.f, 0.f);
            if (row < NN) v = *(const float4*)&x[row * CIN + k0 + (idx & 63)];
            *(float4*)&xs[idx] = v;
        }
        __syncthreads();

        #pragma unroll 4
        for (int k = 0; k < 64; k++) {
            float wv[4];
            #pragma unroll
            for (int j = 0; j < 4; j++) wv[j] = Ws[k * 128 + tx + 32 * j];
            #pragma unroll
            for (int i = 0; i < 8; i++) {
                float xv = xs[(ty + 8 * i) * 64 + k];
                #pragma unroll
                for (int j = 0; j < 4; j++) acc[i][j] += xv * wv[j];
            }
        }
        __syncthreads();
    }

    #pragma unroll
    for (int i = 0; i < 8; i++) {
        int row = base + ty + 8 * i;
        if (row >= NN) continue;
        #pragma unroll
        for (int j = 0; j < 4; j++) {
            int c = tx + 32 * j;
            if (c < 64) g_xl[row * 64 + c]        = acc[i][j];
            else        g_xr[row * 64 + (c - 64)] = acc[i][j];
        }
    }
}

// --------------------- K4: CSR src fill only (no math)
__global__ void k_fill(const int* __restrict__ ei) {
    int e = blockIdx.x * blockDim.x + threadIdx.x;
    if (e >= TE) return;
    int s, d;
    if (e < EE) { s = clampN(ei[e]); d = clampN(ei[EE + e]); }
    else        { s = d = e - EE; }
    int pos = atomicAdd(&g_cursor[d], 1);
    g_srcs[pos] = s;
}

// -------- K5: fused online-softmax aggregation + epilogue (warp per node)
// Per edge: ONE coalesced gather of x_l[s] (prefetched), logit via 5 shfls,
// online max/denom/acc update, then /denom, +bias, ELU, log_softmax.
__global__ void k_aggr(float* __restrict__ out,
                       const float* __restrict__ att,
                       const float* __restrict__ bias) {
    int node = (blockIdx.x * blockDim.x + threadIdx.x) >> 5;
    int lane = threadIdx.x & 31;

    int beg = g_rowptr[node], end = g_rowptr[node + 1];

    float att0 = att[lane],  att1 = att[lane + 32];
    float xr0  = g_xr[node * 64 + lane];
    float xr1  = g_xr[node * 64 + 32 + lane];

    float m = -3.4e38f, denom = 0.f, acc0 = 0.f, acc1 = 0.f;

    // prefetch first edge (degree >= 1 guaranteed by self loops)
    int s = g_srcs[beg];
    float x0 = g_xl[s * 64 + lane];
    float x1 = g_xl[s * 64 + 32 + lane];

    for (int p = beg; p < end; p++) {
        // prefetch next edge's source row
        int sn = (p + 1 < end) ? g_srcs[p + 1] : s;
        float nx0 = g_xl[sn * 64 + lane];
        float nx1 = g_xl[sn * 64 + 32 + lane];

        float e0 = x0 + xr0; e0 = e0 > 0.f ? e0 : 0.2f * e0;
        float e1 = x1 + xr1; e1 = e1 > 0.f ? e1 : 0.2f * e1;
        float part = e0 * att0 + e1 * att1;
        #pragma unroll
        for (int off = 16; off >= 1; off >>= 1)
            part += __shfl_xor_sync(0xffffffffu, part, off);
        // part == logit, replicated on all lanes (warp-uniform)

        if (part <= m) {                 // common path: 1 MUFU
            float a = __expf(part - m);
            denom += a; acc0 += a * x0; acc1 += a * x1;
        } else {                          // new max: rescale (a == 1)
            float sc = __expf(m - part);
            denom = denom * sc + 1.0f;
            acc0  = acc0  * sc + x0;
            acc1  = acc1  * sc + x1;
            m = part;
        }
        x0 = nx0; x1 = nx1;
    }

    float inv = 1.0f / (denom + 1e-16f);
    float v0 = acc0 * inv + bias[lane];
    float v1 = acc1 * inv + bias[lane + 32];

    float h0 = v0 > 0.f ? v0 : (__expf(v0) - 1.0f);
    float h1 = v1 > 0.f ? v1 : (__expf(v1) - 1.0f);

    float mx = fmaxf(h0, h1);
    #pragma unroll
    for (int off = 16; off >= 1; off >>= 1)
        mx = fmaxf(mx, __shfl_xor_sync(0xffffffffu, mx, off));
    float sm = __expf(h0 - mx) + __expf(h1 - mx);
    #pragma unroll
    for (int off = 16; off >= 1; off >>= 1)
        sm += __shfl_xor_sync(0xffffffffu, sm, off);
    float lse = mx + __logf(sm);

    out[node * 64 + lane]      = h0 - lse;
    out[node * 64 + lane + 32] = h1 - lse;
}

// --------------------------------------------------------------------------
extern "C" void kernel_launch(void* const* d_in, const int* in_sizes, int n_in,
                              void* d_out, int out_size) {
    const float* x    = (const float*)d_in[0];
    const int*   ei   = (const int*)d_in[1];     // int32 (JAX x64 disabled)
    const float* Wl   = (const float*)d_in[2];
    const float* Wr   = (const float*)d_in[3];
    const float* att  = (const float*)d_in[4];
    const float* bias = (const float*)d_in[5];
    float*       out  = (float*)d_out;

    k_init<<<(NN + 511) / 512, 512>>>();
    k_count<<<(TE + 255) / 256, 256>>>(ei);
    k_gemm<<<(NN + 63) / 64, 256>>>(x, Wl, Wr);
    k_scanA<<<SCAN_G, SCAN_B>>>();
    k_scanB<<<1, 128>>>();
    k_scanC<<<SCAN_G, SCAN_B>>>();
    k_fill<<<(TE + 255) / 256, 256>>>(ei);
    k_aggr<<<NN * 32 / 256, 256>>>(out, att, bias);
}